// round 1
// baseline (speedup 1.0000x reference)
#include <cuda_runtime.h>
#include <cstddef>

// ---------------- problem constants ----------------
constexpr int B_SZ    = 2;
constexpr int L_SEQ   = 4096;
constexpr int D_MODEL = 1024;
constexpr int D_INNER = 2048;
constexpr int D_STATE = 64;
constexpr int DT_RANK = 128;
constexpr int XDBL_N  = DT_RANK + 2 * D_STATE;   // 256
constexpr int ROWS    = B_SZ * L_SEQ;            // 8192

// ---------------- scratch (device globals; no runtime alloc) ----------------
__device__ float g_xz  [(size_t)ROWS * 2 * D_INNER];   // 128 MB  [b,l, 0:2048]=x pre-conv, [2048:4096]=z
__device__ float g_xact[(size_t)ROWS * D_INNER];       //  64 MB  silu(conv(x))
__device__ float g_xdbl[(size_t)ROWS * XDBL_N];        //   8 MB  [dt_low | B | C]
__device__ float g_dt  [(size_t)ROWS * D_INNER];       //  64 MB  softplus(dt)
__device__ float g_y   [(size_t)ROWS * D_INNER];       //  64 MB  scan output (pre out_proj)

// ---------------- SGEMM: C[M,N] = A[M,K] @ B[N,K]^T ----------------
// BM=BN=128, BK=16, 256 threads, 8x8 per thread. All dims here are multiples
// of the tile sizes, so no bounds checks.
// EPI==1: v = softplus(v + bias[col])
template <int EPI>
__global__ __launch_bounds__(256)
void sgemm_nt(int M, int N, int K,
              const float* __restrict__ A, int lda,
              const float* __restrict__ B,
              const float* __restrict__ bias,
              float* __restrict__ C, int ldc)
{
    __shared__ float As[16][128];
    __shared__ float Bs[16][128];

    const int tid = threadIdx.x;
    const int tx  = tid & 15;
    const int ty  = tid >> 4;
    const int rowBase = blockIdx.y * 128;
    const int colBase = blockIdx.x * 128;

    const float* Ab = A + (size_t)rowBase * lda;
    const float* Bb = B + (size_t)colBase * K;

    float acc[8][8];
#pragma unroll
    for (int i = 0; i < 8; i++)
#pragma unroll
        for (int j = 0; j < 8; j++) acc[i][j] = 0.f;

    for (int k0 = 0; k0 < K; k0 += 16) {
        // cooperative loads: 128x16 tile = 512 float4, 2 per thread, transposed into smem
#pragma unroll
        for (int t = 0; t < 2; t++) {
            int f  = tid * 2 + t;
            int r  = f >> 2;
            int c4 = (f & 3) * 4;
            float4 av = *(const float4*)(Ab + (size_t)r * lda + k0 + c4);
            As[c4 + 0][r] = av.x; As[c4 + 1][r] = av.y;
            As[c4 + 2][r] = av.z; As[c4 + 3][r] = av.w;
            float4 bv = *(const float4*)(Bb + (size_t)r * K + k0 + c4);
            Bs[c4 + 0][r] = bv.x; Bs[c4 + 1][r] = bv.y;
            Bs[c4 + 2][r] = bv.z; Bs[c4 + 3][r] = bv.w;
        }
        __syncthreads();

#pragma unroll
        for (int k = 0; k < 16; k++) {
            float ar[8], br[8];
            *(float4*)(ar)     = *(const float4*)&As[k][ty * 8];
            *(float4*)(ar + 4) = *(const float4*)&As[k][ty * 8 + 4];
            *(float4*)(br)     = *(const float4*)&Bs[k][tx * 8];
            *(float4*)(br + 4) = *(const float4*)&Bs[k][tx * 8 + 4];
#pragma unroll
            for (int i = 0; i < 8; i++)
#pragma unroll
                for (int j = 0; j < 8; j++)
                    acc[i][j] = fmaf(ar[i], br[j], acc[i][j]);
        }
        __syncthreads();
    }

#pragma unroll
    for (int i = 0; i < 8; i++) {
        int row = rowBase + ty * 8 + i;
#pragma unroll
        for (int j = 0; j < 8; j++) {
            int col = colBase + tx * 8 + j;
            float v = acc[i][j];
            if (EPI == 1) {
                v += bias[col];
                // numerically stable softplus
                v = fmaxf(v, 0.f) + log1pf(expf(-fabsf(v)));
            }
            C[(size_t)row * ldc + col] = v;
        }
    }
}

// ---------------- depthwise causal conv(4) + bias + SiLU ----------------
__global__ __launch_bounds__(256)
void conv_silu_kernel(const float* __restrict__ xz,
                      const float* __restrict__ w,    // [D_INNER][4]
                      const float* __restrict__ cb,   // [D_INNER]
                      float* __restrict__ xact)
{
    int idx = blockIdx.x * blockDim.x + threadIdx.x;   // over B*L*D_INNER = 16,777,216
    const int total = B_SZ * L_SEQ * D_INNER;
    if (idx >= total) return;
    int d = idx & (D_INNER - 1);
    int l = (idx >> 11) & (L_SEQ - 1);
    int b = idx >> 23;

    const float* base = xz + (size_t)b * L_SEQ * (2 * D_INNER) + d;  // x lives at cols [0,2048)
    float acc = cb[d];
#pragma unroll
    for (int j = 0; j < 4; j++) {
        int ll = l - 3 + j;
        if (ll >= 0)
            acc = fmaf(w[d * 4 + j], base[(size_t)ll * (2 * D_INNER)], acc);
    }
    float s = 1.f / (1.f + __expf(-acc));
    xact[idx] = acc * s;
}

// ---------------- selective scan (1 warp / channel, 2 states / lane) ----------------
// Fuses:  y_t = (sum_n h_t[n]*C_t[n] + D[d]*x_t) * silu(z_t)
__global__ __launch_bounds__(256)
void scan_kernel(const float* __restrict__ dt,     // [b,l,D_INNER]
                 const float* __restrict__ xact,   // [b,l,D_INNER]
                 const float* __restrict__ xdbl,   // [b,l,256]  (B at 128, C at 192)
                 const float* __restrict__ xz,     // z at [b,l,2048+d]
                 const float* __restrict__ A_log,  // [D_INNER, 64]
                 const float* __restrict__ Dvec,   // [D_INNER]
                 float* __restrict__ y)            // [b,l,D_INNER]
{
    int warp = (blockIdx.x * blockDim.x + threadIdx.x) >> 5;
    int lane = threadIdx.x & 31;
    if (warp >= B_SZ * D_INNER) return;
    int b = warp / D_INNER;
    int d = warp % D_INNER;

    const float a0 = -__expf(A_log[d * D_STATE + lane]);
    const float a1 = -__expf(A_log[d * D_STATE + lane + 32]);
    const float Dd = Dvec[d];

    const float* dtp = dt   + (size_t)b * L_SEQ * D_INNER + d;
    const float* xp  = xact + (size_t)b * L_SEQ * D_INNER + d;
    const float* Bp  = xdbl + (size_t)b * L_SEQ * XDBL_N + DT_RANK + lane;
    const float* Cp  = Bp + D_STATE;
    const float* zp  = xz   + (size_t)b * L_SEQ * (2 * D_INNER) + D_INNER + d;
    float*       yp  = y    + (size_t)b * L_SEQ * D_INNER + d;

    float h0 = 0.f, h1 = 0.f;

#pragma unroll 2
    for (int l = 0; l < L_SEQ; l++) {
        float dtv = __ldg(dtp);
        float xv  = __ldg(xp);
        float b0  = __ldg(Bp);
        float b1  = __ldg(Bp + 32);
        float c0  = __ldg(Cp);
        float c1  = __ldg(Cp + 32);

        float du  = dtv * xv;
        h0 = fmaf(h0, __expf(dtv * a0), du * b0);
        h1 = fmaf(h1, __expf(dtv * a1), du * b1);

        float ys = fmaf(h0, c0, h1 * c1);
#pragma unroll
        for (int o = 16; o; o >>= 1)
            ys += __shfl_xor_sync(0xffffffffu, ys, o);

        if (lane == 0) {
            float zv = __ldg(zp);
            float sz = zv / (1.f + __expf(-zv));
            *yp = (ys + Dd * xv) * sz;
        }

        dtp += D_INNER; xp += D_INNER;
        Bp  += XDBL_N;  Cp += XDBL_N;
        zp  += 2 * D_INNER; yp += D_INNER;
    }
}

// ---------------- launch ----------------
extern "C" void kernel_launch(void* const* d_in, const int* in_sizes, int n_in,
                              void* d_out, int out_size)
{
    const float* hs        = (const float*)d_in[0];
    const float* in_proj_w = (const float*)d_in[1];
    const float* conv_w    = (const float*)d_in[2];
    const float* conv_b    = (const float*)d_in[3];
    const float* x_proj_w  = (const float*)d_in[4];
    const float* dt_proj_w = (const float*)d_in[5];
    const float* dt_proj_b = (const float*)d_in[6];
    const float* A_log     = (const float*)d_in[7];
    const float* Dv        = (const float*)d_in[8];
    const float* out_proj_w= (const float*)d_in[9];
    float* out = (float*)d_out;

    float *xz, *xact, *xdbl, *dtb, *yb;
    cudaGetSymbolAddress((void**)&xz,   g_xz);
    cudaGetSymbolAddress((void**)&xact, g_xact);
    cudaGetSymbolAddress((void**)&xdbl, g_xdbl);
    cudaGetSymbolAddress((void**)&dtb,  g_dt);
    cudaGetSymbolAddress((void**)&yb,   g_y);

    // 1) xz = hs @ in_proj_w^T   [8192 x 4096]
    sgemm_nt<0><<<dim3((2 * D_INNER) / 128, ROWS / 128), 256>>>(
        ROWS, 2 * D_INNER, D_MODEL, hs, D_MODEL, in_proj_w, nullptr, xz, 2 * D_INNER);

    // 2) x = silu(causal_conv4(x) + b)
    {
        int total = B_SZ * L_SEQ * D_INNER;
        conv_silu_kernel<<<(total + 255) / 256, 256>>>(xz, conv_w, conv_b, xact);
    }

    // 3) x_dbl = x @ x_proj_w^T   [8192 x 256]
    sgemm_nt<0><<<dim3(XDBL_N / 128, ROWS / 128), 256>>>(
        ROWS, XDBL_N, D_INNER, xact, D_INNER, x_proj_w, nullptr, xdbl, XDBL_N);

    // 4) dt = softplus(dt_low @ dt_proj_w^T + dt_proj_b)   [8192 x 2048]
    sgemm_nt<1><<<dim3(D_INNER / 128, ROWS / 128), 256>>>(
        ROWS, D_INNER, DT_RANK, xdbl, XDBL_N, dt_proj_w, dt_proj_b, dtb, D_INNER);

    // 5) selective scan + gating epilogue -> yb
    {
        int warps  = B_SZ * D_INNER;          // 4096
        int blocks = (warps * 32) / 256;      // 512
        scan_kernel<<<blocks, 256>>>(dtb, xact, xdbl, xz, A_log, Dv, yb);
    }

    // 6) out = y @ out_proj_w^T   [8192 x 1024]
    sgemm_nt<0><<<dim3(D_MODEL / 128, ROWS / 128), 256>>>(
        ROWS, D_MODEL, D_INNER, yb, D_INNER, out_proj_w, nullptr, out, D_MODEL);
}

// round 2
// speedup vs baseline: 1.2940x; 1.2940x over previous
#include <cuda_runtime.h>
#include <cstdint>
#include <cstddef>

// ---------------- problem constants ----------------
constexpr int B_SZ    = 2;
constexpr int L_SEQ   = 4096;
constexpr int D_MODEL = 1024;
constexpr int D_INNER = 2048;
constexpr int D_STATE = 64;
constexpr int DT_RANK = 128;
constexpr int XDBL_N  = DT_RANK + 2 * D_STATE;   // 256
constexpr int ROWS    = B_SZ * L_SEQ;            // 8192

// ---------------- scratch (device globals; no runtime alloc) ----------------
__device__ __align__(16) float g_xz  [(size_t)ROWS * 2 * D_INNER];
__device__ __align__(16) float g_xact[(size_t)ROWS * D_INNER];
__device__ __align__(16) float g_xdbl[(size_t)ROWS * XDBL_N];
__device__ __align__(16) float g_dt  [(size_t)ROWS * D_INNER];
__device__ __align__(16) float g_y   [(size_t)ROWS * D_INNER];

// ---------------- helpers ----------------
__device__ __forceinline__ float to_tf32(float x) {
    uint32_t u;
    asm("cvt.rna.tf32.f32 %0, %1;" : "=r"(u) : "f"(x));
    return __uint_as_float(u);
}

__device__ __forceinline__ void mma_tf32(float c[4],
                                         uint32_t a0, uint32_t a1, uint32_t a2, uint32_t a3,
                                         uint32_t b0, uint32_t b1) {
    asm volatile(
        "mma.sync.aligned.m16n8k8.row.col.f32.tf32.tf32.f32 "
        "{%0,%1,%2,%3}, {%4,%5,%6,%7}, {%8,%9}, {%0,%1,%2,%3};"
        : "+f"(c[0]), "+f"(c[1]), "+f"(c[2]), "+f"(c[3])
        : "r"(a0), "r"(a1), "r"(a2), "r"(a3), "r"(b0), "r"(b1));
}

// ---------------- TF32 tensor-core GEMM: C[M,N] = A[M,K] @ B[N,K]^T ----------
// BM=BN=128, BK=16, 256 threads (8 warps as 2x4), warp tile 64x32.
// smem rows padded to 136 floats -> fragment LDS bank = (8*tig+gid)%32 is a
// permutation (conflict-free). Double-buffered with register staging.
__global__ __launch_bounds__(256)
void gemm_tf32(int M, int N, int K,
               const float* __restrict__ A, int lda,
               const float* __restrict__ B,
               float* __restrict__ C, int ldc)
{
    __shared__ float As[2][16][136];
    __shared__ float Bs[2][16][136];

    const int tid     = threadIdx.x;
    const int lane    = tid & 31;
    const int warp    = tid >> 5;
    const int wm      = warp >> 2;   // 0..1
    const int wn      = warp & 3;    // 0..3
    const int gid     = lane >> 2;   // 0..7
    const int tig     = lane & 3;    // 0..3
    const int rowBase = blockIdx.y * 128;
    const int colBase = blockIdx.x * 128;

    const float* Ab = A + (size_t)rowBase * lda;
    const float* Bb = B + (size_t)colBase * K;

    float acc[4][4][4];
#pragma unroll
    for (int mi = 0; mi < 4; mi++)
#pragma unroll
        for (int ni = 0; ni < 4; ni++)
#pragma unroll
            for (int r = 0; r < 4; r++) acc[mi][ni][r] = 0.f;

    float4 ra[2], rb[2];

    auto gload = [&](int k0) {
#pragma unroll
        for (int t = 0; t < 2; t++) {
            int f  = tid * 2 + t;
            int r  = f >> 2;
            int c4 = (f & 3) * 4;
            ra[t] = *(const float4*)(Ab + (size_t)r * lda + k0 + c4);
            rb[t] = *(const float4*)(Bb + (size_t)r * K   + k0 + c4);
        }
    };
    auto sstore = [&](int buf) {
#pragma unroll
        for (int t = 0; t < 2; t++) {
            int f  = tid * 2 + t;
            int r  = f >> 2;
            int c4 = (f & 3) * 4;
            As[buf][c4 + 0][r] = to_tf32(ra[t].x);
            As[buf][c4 + 1][r] = to_tf32(ra[t].y);
            As[buf][c4 + 2][r] = to_tf32(ra[t].z);
            As[buf][c4 + 3][r] = to_tf32(ra[t].w);
            Bs[buf][c4 + 0][r] = to_tf32(rb[t].x);
            Bs[buf][c4 + 1][r] = to_tf32(rb[t].y);
            Bs[buf][c4 + 2][r] = to_tf32(rb[t].z);
            Bs[buf][c4 + 3][r] = to_tf32(rb[t].w);
        }
    };
    auto compute = [&](int buf) {
#pragma unroll
        for (int ks = 0; ks < 2; ks++) {
            const int k = ks * 8 + tig;
            uint32_t af[4][4];
#pragma unroll
            for (int mi = 0; mi < 4; mi++) {
                int m = wm * 64 + mi * 16 + gid;
                af[mi][0] = __float_as_uint(As[buf][k][m]);
                af[mi][1] = __float_as_uint(As[buf][k][m + 8]);
                af[mi][2] = __float_as_uint(As[buf][k + 4][m]);
                af[mi][3] = __float_as_uint(As[buf][k + 4][m + 8]);
            }
            uint32_t bf[4][2];
#pragma unroll
            for (int ni = 0; ni < 4; ni++) {
                int n = wn * 32 + ni * 8 + gid;
                bf[ni][0] = __float_as_uint(Bs[buf][k][n]);
                bf[ni][1] = __float_as_uint(Bs[buf][k + 4][n]);
            }
#pragma unroll
            for (int mi = 0; mi < 4; mi++)
#pragma unroll
                for (int ni = 0; ni < 4; ni++)
                    mma_tf32(acc[mi][ni], af[mi][0], af[mi][1], af[mi][2], af[mi][3],
                             bf[ni][0], bf[ni][1]);
        }
    };

    const int nIter = K / 16;
    gload(0);
    sstore(0);
    __syncthreads();

    for (int i = 0; i < nIter; i++) {
        int buf = i & 1;
        if (i + 1 < nIter) gload((i + 1) * 16);
        compute(buf);
        if (i + 1 < nIter) {
            sstore(buf ^ 1);
            __syncthreads();
        }
    }

    // epilogue: c0 (gid, 2tig), c1 (gid, 2tig+1), c2 (gid+8, 2tig), c3 (gid+8, 2tig+1)
#pragma unroll
    for (int mi = 0; mi < 4; mi++) {
#pragma unroll
        for (int ni = 0; ni < 4; ni++) {
            int row0 = rowBase + wm * 64 + mi * 16 + gid;
            int col  = colBase + wn * 32 + ni * 8 + 2 * tig;
            float2 v0 = make_float2(acc[mi][ni][0], acc[mi][ni][1]);
            float2 v1 = make_float2(acc[mi][ni][2], acc[mi][ni][3]);
            *(float2*)(C + (size_t)row0 * ldc + col)       = v0;
            *(float2*)(C + (size_t)(row0 + 8) * ldc + col) = v1;
        }
    }
}

// ---------------- fp32 SIMT SGEMM (kept for dt_proj precision path) --------
// C[M,N] = A[M,K] @ B[N,K]^T ; EPI==1: v = softplus(v + bias[col])
template <int EPI>
__global__ __launch_bounds__(256)
void sgemm_nt(int M, int N, int K,
              const float* __restrict__ A, int lda,
              const float* __restrict__ B,
              const float* __restrict__ bias,
              float* __restrict__ C, int ldc)
{
    __shared__ float As[16][128];
    __shared__ float Bs[16][128];

    const int tid = threadIdx.x;
    const int tx  = tid & 15;
    const int ty  = tid >> 4;
    const int rowBase = blockIdx.y * 128;
    const int colBase = blockIdx.x * 128;

    const float* Ab = A + (size_t)rowBase * lda;
    const float* Bb = B + (size_t)colBase * K;

    float acc[8][8];
#pragma unroll
    for (int i = 0; i < 8; i++)
#pragma unroll
        for (int j = 0; j < 8; j++) acc[i][j] = 0.f;

    for (int k0 = 0; k0 < K; k0 += 16) {
#pragma unroll
        for (int t = 0; t < 2; t++) {
            int f  = tid * 2 + t;
            int r  = f >> 2;
            int c4 = (f & 3) * 4;
            float4 av = *(const float4*)(Ab + (size_t)r * lda + k0 + c4);
            As[c4 + 0][r] = av.x; As[c4 + 1][r] = av.y;
            As[c4 + 2][r] = av.z; As[c4 + 3][r] = av.w;
            float4 bv = *(const float4*)(Bb + (size_t)r * K + k0 + c4);
            Bs[c4 + 0][r] = bv.x; Bs[c4 + 1][r] = bv.y;
            Bs[c4 + 2][r] = bv.z; Bs[c4 + 3][r] = bv.w;
        }
        __syncthreads();

#pragma unroll
        for (int k = 0; k < 16; k++) {
            float ar[8], br[8];
            *(float4*)(ar)     = *(const float4*)&As[k][ty * 8];
            *(float4*)(ar + 4) = *(const float4*)&As[k][ty * 8 + 4];
            *(float4*)(br)     = *(const float4*)&Bs[k][tx * 8];
            *(float4*)(br + 4) = *(const float4*)&Bs[k][tx * 8 + 4];
#pragma unroll
            for (int i = 0; i < 8; i++)
#pragma unroll
                for (int j = 0; j < 8; j++)
                    acc[i][j] = fmaf(ar[i], br[j], acc[i][j]);
        }
        __syncthreads();
    }

#pragma unroll
    for (int i = 0; i < 8; i++) {
        int row = rowBase + ty * 8 + i;
#pragma unroll
        for (int j = 0; j < 8; j++) {
            int col = colBase + tx * 8 + j;
            float v = acc[i][j];
            if (EPI == 1) {
                v += bias[col];
                v = fmaxf(v, 0.f) + log1pf(expf(-fabsf(v)));
            }
            C[(size_t)row * ldc + col] = v;
        }
    }
}

// ---------------- depthwise causal conv(4) + bias + SiLU ----------------
__global__ __launch_bounds__(256)
void conv_silu_kernel(const float* __restrict__ xz,
                      const float* __restrict__ w,
                      const float* __restrict__ cb,
                      float* __restrict__ xact)
{
    int idx = blockIdx.x * blockDim.x + threadIdx.x;
    const int total = B_SZ * L_SEQ * D_INNER;
    if (idx >= total) return;
    int d = idx & (D_INNER - 1);
    int l = (idx >> 11) & (L_SEQ - 1);
    int b = idx >> 23;

    const float* base = xz + (size_t)b * L_SEQ * (2 * D_INNER) + d;
    float acc = cb[d];
#pragma unroll
    for (int j = 0; j < 4; j++) {
        int ll = l - 3 + j;
        if (ll >= 0)
            acc = fmaf(w[d * 4 + j], base[(size_t)ll * (2 * D_INNER)], acc);
    }
    float s = 1.f / (1.f + __expf(-acc));
    xact[idx] = acc * s;
}

// ---------------- selective scan (1 warp / channel, 2 states / lane) --------
__global__ __launch_bounds__(256)
void scan_kernel(const float* __restrict__ dt,
                 const float* __restrict__ xact,
                 const float* __restrict__ xdbl,
                 const float* __restrict__ xz,
                 const float* __restrict__ A_log,
                 const float* __restrict__ Dvec,
                 float* __restrict__ y)
{
    int warp = (blockIdx.x * blockDim.x + threadIdx.x) >> 5;
    int lane = threadIdx.x & 31;
    if (warp >= B_SZ * D_INNER) return;
    int b = warp / D_INNER;
    int d = warp % D_INNER;

    const float a0 = -__expf(A_log[d * D_STATE + lane]);
    const float a1 = -__expf(A_log[d * D_STATE + lane + 32]);
    const float Dd = Dvec[d];

    const float* dtp = dt   + (size_t)b * L_SEQ * D_INNER + d;
    const float* xp  = xact + (size_t)b * L_SEQ * D_INNER + d;
    const float* Bp  = xdbl + (size_t)b * L_SEQ * XDBL_N + DT_RANK + lane;
    const float* Cp  = Bp + D_STATE;
    const float* zp  = xz   + (size_t)b * L_SEQ * (2 * D_INNER) + D_INNER + d;
    float*       yp  = y    + (size_t)b * L_SEQ * D_INNER + d;

    float h0 = 0.f, h1 = 0.f;

#pragma unroll 2
    for (int l = 0; l < L_SEQ; l++) {
        float dtv = __ldg(dtp);
        float xv  = __ldg(xp);
        float b0  = __ldg(Bp);
        float b1  = __ldg(Bp + 32);
        float c0  = __ldg(Cp);
        float c1  = __ldg(Cp + 32);

        float du  = dtv * xv;
        h0 = fmaf(h0, __expf(dtv * a0), du * b0);
        h1 = fmaf(h1, __expf(dtv * a1), du * b1);

        float ys = fmaf(h0, c0, h1 * c1);
#pragma unroll
        for (int o = 16; o; o >>= 1)
            ys += __shfl_xor_sync(0xffffffffu, ys, o);

        if (lane == 0) {
            float zv = __ldg(zp);
            float sz = zv / (1.f + __expf(-zv));
            *yp = (ys + Dd * xv) * sz;
        }

        dtp += D_INNER; xp += D_INNER;
        Bp  += XDBL_N;  Cp += XDBL_N;
        zp  += 2 * D_INNER; yp += D_INNER;
    }
}

// ---------------- launch ----------------
extern "C" void kernel_launch(void* const* d_in, const int* in_sizes, int n_in,
                              void* d_out, int out_size)
{
    const float* hs        = (const float*)d_in[0];
    const float* in_proj_w = (const float*)d_in[1];
    const float* conv_w    = (const float*)d_in[2];
    const float* conv_b    = (const float*)d_in[3];
    const float* x_proj_w  = (const float*)d_in[4];
    const float* dt_proj_w = (const float*)d_in[5];
    const float* dt_proj_b = (const float*)d_in[6];
    const float* A_log     = (const float*)d_in[7];
    const float* Dv        = (const float*)d_in[8];
    const float* out_proj_w= (const float*)d_in[9];
    float* out = (float*)d_out;

    float *xz, *xact, *xdbl, *dtb, *yb;
    cudaGetSymbolAddress((void**)&xz,   g_xz);
    cudaGetSymbolAddress((void**)&xact, g_xact);
    cudaGetSymbolAddress((void**)&xdbl, g_xdbl);
    cudaGetSymbolAddress((void**)&dtb,  g_dt);
    cudaGetSymbolAddress((void**)&yb,   g_y);

    // 1) xz = hs @ in_proj_w^T   [8192 x 4096]  (tf32 tensor cores)
    gemm_tf32<<<dim3((2 * D_INNER) / 128, ROWS / 128), 256>>>(
        ROWS, 2 * D_INNER, D_MODEL, hs, D_MODEL, in_proj_w, xz, 2 * D_INNER);

    // 2) x = silu(causal_conv4(x) + b)
    {
        int total = B_SZ * L_SEQ * D_INNER;
        conv_silu_kernel<<<(total + 255) / 256, 256>>>(xz, conv_w, conv_b, xact);
    }

    // 3) x_dbl = x @ x_proj_w^T   [8192 x 256]  (tf32 tensor cores)
    gemm_tf32<<<dim3(XDBL_N / 128, ROWS / 128), 256>>>(
        ROWS, XDBL_N, D_INNER, xact, D_INNER, x_proj_w, xdbl, XDBL_N);

    // 4) dt = softplus(dt_low @ dt_proj_w^T + dt_proj_b)  (fp32 SIMT, precision)
    sgemm_nt<1><<<dim3(D_INNER / 128, ROWS / 128), 256>>>(
        ROWS, D_INNER, DT_RANK, xdbl, XDBL_N, dt_proj_w, dt_proj_b, dtb, D_INNER);

    // 5) selective scan + gating epilogue -> yb
    {
        int warps  = B_SZ * D_INNER;
        int blocks = (warps * 32) / 256;
        scan_kernel<<<blocks, 256>>>(dtb, xact, xdbl, xz, A_log, Dv, yb);
    }

    // 6) out = y @ out_proj_w^T   [8192 x 1024]  (tf32 tensor cores)
    gemm_tf32<<<dim3(D_MODEL / 128, ROWS / 128), 256>>>(
        ROWS, D_MODEL, D_INNER, yb, D_INNER, out_proj_w, out, D_MODEL);
}

// round 4
// speedup vs baseline: 3.3888x; 2.6190x over previous
#include <cuda_runtime.h>
#include <cstdint>
#include <cstddef>

// ---------------- problem constants ----------------
constexpr int B_SZ    = 2;
constexpr int L_SEQ   = 4096;
constexpr int D_MODEL = 1024;
constexpr int D_INNER = 2048;
constexpr int D_STATE = 64;
constexpr int DT_RANK = 128;
constexpr int XDBL_N  = DT_RANK + 2 * D_STATE;   // 256
constexpr int ROWS    = B_SZ * L_SEQ;            // 8192

// ---------------- scratch (device globals; no runtime alloc) ----------------
__device__ __align__(16) float g_xz    [(size_t)ROWS * 2 * D_INNER];
__device__ __align__(16) float g_xact  [(size_t)ROWS * D_INNER];   // fp32 (scan)
__device__ __align__(16) float g_xact_r[(size_t)ROWS * D_INNER];   // tf32-rounded (gemm)
__device__ __align__(16) float g_xdbl  [(size_t)ROWS * XDBL_N];
__device__ __align__(16) float g_dt    [(size_t)ROWS * D_INNER];
__device__ __align__(16) float g_y     [(size_t)ROWS * D_INNER];   // tf32-rounded by scan
__device__ __align__(16) float g_hs_r  [(size_t)ROWS * D_MODEL];
__device__ __align__(16) float g_wi_r  [(size_t)2 * D_INNER * D_MODEL];
__device__ __align__(16) float g_wx_r  [(size_t)XDBL_N * D_INNER];
__device__ __align__(16) float g_wo_r  [(size_t)D_MODEL * D_INNER];

// ---------------- helpers ----------------
__device__ __forceinline__ float to_tf32(float x) {
    uint32_t u;
    asm("cvt.rna.tf32.f32 %0, %1;" : "=r"(u) : "f"(x));
    return __uint_as_float(u);
}
__device__ __forceinline__ float ex2(float x) {   // 2^x, MUFU.EX2
    float r;
    asm("ex2.approx.f32 %0, %1;" : "=f"(r) : "f"(x));
    return r;
}
__device__ __forceinline__ uint32_t smem_u32(const void* p) {
    uint32_t a;
    asm("{ .reg .u64 t; cvta.to.shared.u64 t, %1; cvt.u32.u64 %0, t; }" : "=r"(a) : "l"(p));
    return a;
}
__device__ __forceinline__ void cp16(uint32_t saddr, const void* g) {
    asm volatile("cp.async.cg.shared.global [%0], [%1], 16;" :: "r"(saddr), "l"(g) : "memory");
}
__device__ __forceinline__ void mma_tf32(float c[4],
                                         uint32_t a0, uint32_t a1, uint32_t a2, uint32_t a3,
                                         uint32_t b0, uint32_t b1) {
    asm volatile(
        "mma.sync.aligned.m16n8k8.row.col.f32.tf32.tf32.f32 "
        "{%0,%1,%2,%3}, {%4,%5,%6,%7}, {%8,%9}, {%0,%1,%2,%3};"
        : "+f"(c[0]), "+f"(c[1]), "+f"(c[2]), "+f"(c[3])
        : "r"(a0), "r"(a1), "r"(a2), "r"(a3), "r"(b0), "r"(b1));
}

// ================= TF32 mma.sync GEMM: C[M,N] = A[M,K] @ B[N,K]^T ============
// BM=BN=128, BK=16, 256 threads (8 warps 2x4), warp tile 64x32.
// 3-stage cp.async pipeline. smem tiles [128][20] floats (16B-aligned rows,
// conflict-free fragment reads). Operands must be pre-rounded to tf32.
constexpr int G_STAGES   = 3;
constexpr int TILE_FLTS  = 128 * 20;                        // per operand per stage
constexpr int STAGE_FLTS = 2 * TILE_FLTS;                   // A + B
constexpr int GEMM_SMEM  = G_STAGES * STAGE_FLTS * 4;       // 61440 B

__global__ __launch_bounds__(256)
void gemm_tc(int K, const float* __restrict__ A, int lda,
             const float* __restrict__ B, int ldb,
             float* __restrict__ C, int ldc)
{
    extern __shared__ float sm[];
    const uint32_t sbase = smem_u32(sm);

    const int tid     = threadIdx.x;
    const int lane    = tid & 31;
    const int warp    = tid >> 5;
    const int wm      = warp >> 2;
    const int wn      = warp & 3;
    const int gid     = lane >> 2;
    const int tig     = lane & 3;
    const int rowBase = blockIdx.y * 128;
    const int colBase = blockIdx.x * 128;
    const int T       = K / 16;

    // this thread's two cp.async fragments: f = tid*2 + t -> row r, k-offset c4
    const int r0  = (tid * 2) >> 2;
    const int c40 = ((tid * 2) & 3) * 4;
    const int r1  = (tid * 2 + 1) >> 2;
    const int c41 = ((tid * 2 + 1) & 3) * 4;

    const float* Ab = A + (size_t)rowBase * lda;
    const float* Bb = B + (size_t)colBase * ldb;

    auto load_stage = [&](int t, int slot) {
        uint32_t sa = sbase + (uint32_t)(slot * STAGE_FLTS) * 4;
        uint32_t sb = sa + TILE_FLTS * 4;
        int k0 = t * 16;
        cp16(sa + (uint32_t)(r0 * 20 + c40) * 4, Ab + (size_t)r0 * lda + k0 + c40);
        cp16(sa + (uint32_t)(r1 * 20 + c41) * 4, Ab + (size_t)r1 * lda + k0 + c41);
        cp16(sb + (uint32_t)(r0 * 20 + c40) * 4, Bb + (size_t)r0 * ldb + k0 + c40);
        cp16(sb + (uint32_t)(r1 * 20 + c41) * 4, Bb + (size_t)r1 * ldb + k0 + c41);
    };

    float acc[4][4][4];
#pragma unroll
    for (int mi = 0; mi < 4; mi++)
#pragma unroll
        for (int ni = 0; ni < 4; ni++)
#pragma unroll
            for (int r = 0; r < 4; r++) acc[mi][ni][r] = 0.f;

#pragma unroll
    for (int s = 0; s < G_STAGES; s++) {
        load_stage(s, s);
        asm volatile("cp.async.commit_group;" ::: "memory");
    }

    for (int t = 0; t < T; t++) {
        const int slot = t % G_STAGES;
        asm volatile("cp.async.wait_group %0;" :: "n"(G_STAGES - 1) : "memory");
        __syncthreads();

        const float* As = sm + slot * STAGE_FLTS;
        const float* Bs = As + TILE_FLTS;

#pragma unroll
        for (int ks = 0; ks < 2; ks++) {
            const int k = ks * 8 + tig;
            uint32_t af[4][4];
#pragma unroll
            for (int mi = 0; mi < 4; mi++) {
                int m = wm * 64 + mi * 16 + gid;
                af[mi][0] = __float_as_uint(As[m * 20 + k]);
                af[mi][1] = __float_as_uint(As[(m + 8) * 20 + k]);
                af[mi][2] = __float_as_uint(As[m * 20 + k + 4]);
                af[mi][3] = __float_as_uint(As[(m + 8) * 20 + k + 4]);
            }
            uint32_t bf[4][2];
#pragma unroll
            for (int ni = 0; ni < 4; ni++) {
                int n = wn * 32 + ni * 8 + gid;
                bf[ni][0] = __float_as_uint(Bs[n * 20 + k]);
                bf[ni][1] = __float_as_uint(Bs[n * 20 + k + 4]);
            }
#pragma unroll
            for (int mi = 0; mi < 4; mi++)
#pragma unroll
                for (int ni = 0; ni < 4; ni++)
                    mma_tf32(acc[mi][ni], af[mi][0], af[mi][1], af[mi][2], af[mi][3],
                             bf[ni][0], bf[ni][1]);
        }

        __syncthreads();
        if (t + G_STAGES < T) load_stage(t + G_STAGES, slot);
        asm volatile("cp.async.commit_group;" ::: "memory");
    }

#pragma unroll
    for (int mi = 0; mi < 4; mi++) {
#pragma unroll
        for (int ni = 0; ni < 4; ni++) {
            int row0 = rowBase + wm * 64 + mi * 16 + gid;
            int col  = colBase + wn * 32 + ni * 8 + 2 * tig;
            *(float2*)(C + (size_t)row0 * ldc + col)       = make_float2(acc[mi][ni][0], acc[mi][ni][1]);
            *(float2*)(C + (size_t)(row0 + 8) * ldc + col) = make_float2(acc[mi][ni][2], acc[mi][ni][3]);
        }
    }
}

// ---------------- tf32 rounding pass ----------------
__global__ __launch_bounds__(256)
void round_tf32_kernel(const float* __restrict__ in, float* __restrict__ out, int n4)
{
    int i = blockIdx.x * blockDim.x + threadIdx.x;
    if (i >= n4) return;
    float4 v = ((const float4*)in)[i];
    v.x = to_tf32(v.x); v.y = to_tf32(v.y); v.z = to_tf32(v.z); v.w = to_tf32(v.w);
    ((float4*)out)[i] = v;
}

// ---------------- fp32 SIMT SGEMM (dt_proj precision path) ----------------
template <int EPI>
__global__ __launch_bounds__(256)
void sgemm_nt(int M, int N, int K,
              const float* __restrict__ A, int lda,
              const float* __restrict__ B,
              const float* __restrict__ bias,
              float* __restrict__ C, int ldc)
{
    __shared__ float As[16][128];
    __shared__ float Bs[16][128];

    const int tid = threadIdx.x;
    const int tx  = tid & 15;
    const int ty  = tid >> 4;
    const int rowBase = blockIdx.y * 128;
    const int colBase = blockIdx.x * 128;

    const float* Ab = A + (size_t)rowBase * lda;
    const float* Bb = B + (size_t)colBase * K;

    float acc[8][8];
#pragma unroll
    for (int i = 0; i < 8; i++)
#pragma unroll
        for (int j = 0; j < 8; j++) acc[i][j] = 0.f;

    for (int k0 = 0; k0 < K; k0 += 16) {
#pragma unroll
        for (int t = 0; t < 2; t++) {
            int f  = tid * 2 + t;
            int r  = f >> 2;
            int c4 = (f & 3) * 4;
            float4 av = *(const float4*)(Ab + (size_t)r * lda + k0 + c4);
            As[c4 + 0][r] = av.x; As[c4 + 1][r] = av.y;
            As[c4 + 2][r] = av.z; As[c4 + 3][r] = av.w;
            float4 bv = *(const float4*)(Bb + (size_t)r * K + k0 + c4);
            Bs[c4 + 0][r] = bv.x; Bs[c4 + 1][r] = bv.y;
            Bs[c4 + 2][r] = bv.z; Bs[c4 + 3][r] = bv.w;
        }
        __syncthreads();

#pragma unroll
        for (int k = 0; k < 16; k++) {
            float ar[8], br[8];
            *(float4*)(ar)     = *(const float4*)&As[k][ty * 8];
            *(float4*)(ar + 4) = *(const float4*)&As[k][ty * 8 + 4];
            *(float4*)(br)     = *(const float4*)&Bs[k][tx * 8];
            *(float4*)(br + 4) = *(const float4*)&Bs[k][tx * 8 + 4];
#pragma unroll
            for (int i = 0; i < 8; i++)
#pragma unroll
                for (int j = 0; j < 8; j++)
                    acc[i][j] = fmaf(ar[i], br[j], acc[i][j]);
        }
        __syncthreads();
    }

#pragma unroll
    for (int i = 0; i < 8; i++) {
        int row = rowBase + ty * 8 + i;
#pragma unroll
        for (int j = 0; j < 8; j++) {
            int col = colBase + tx * 8 + j;
            float v = acc[i][j];
            if (EPI == 1) {
                v += bias[col];
                v = fmaxf(v, 0.f) + log1pf(expf(-fabsf(v)));
            }
            C[(size_t)row * ldc + col] = v;
        }
    }
}

// ---------------- depthwise causal conv(4) + bias + SiLU ----------------
__global__ __launch_bounds__(256)
void conv_silu_kernel(const float* __restrict__ xz,
                      const float* __restrict__ w,
                      const float* __restrict__ cb,
                      float* __restrict__ xact,
                      float* __restrict__ xact_r)
{
    int idx = blockIdx.x * blockDim.x + threadIdx.x;
    const int total = B_SZ * L_SEQ * D_INNER;
    if (idx >= total) return;
    int d = idx & (D_INNER - 1);
    int l = (idx >> 11) & (L_SEQ - 1);
    int b = idx >> 23;

    const float* base = xz + (size_t)b * L_SEQ * (2 * D_INNER) + d;
    float acc = cb[d];
#pragma unroll
    for (int j = 0; j < 4; j++) {
        int ll = l - 3 + j;
        if (ll >= 0)
            acc = fmaf(w[d * 4 + j], base[(size_t)ll * (2 * D_INNER)], acc);
    }
    float s = 1.f / (1.f + __expf(-acc));
    float v = acc * s;
    xact[idx]   = v;
    xact_r[idx] = to_tf32(v);
}

// ---------------- selective scan v3: smem-tiled, coalesced ------------------
// Block = 1024 threads (32 warps) = one (batch, 32-channel) slice over all L.
// Per 32-step tile: stage dt/x tiles (32x32) and B|C tile (32x128) in smem;
// each warp runs its channel out of smem; gating + D*x + tf32 rounding fused
// into the coalesced y-tile store.
constexpr int SC_WARPS = 32;
constexpr int SC_TILE  = 32;   // steps per tile

__global__ __launch_bounds__(1024)
void scan_kernel(const float* __restrict__ dt,
                 const float* __restrict__ xact,
                 const float* __restrict__ xdbl,
                 const float* __restrict__ xz,
                 const float* __restrict__ A_log,
                 const float* __restrict__ Dvec,
                 float* __restrict__ y)
{
    __shared__ float dt_s[SC_TILE][33];
    __shared__ float x_s [SC_TILE][33];
    __shared__ float y_s [SC_TILE][33];
    __shared__ float bc_s[SC_TILE][128];   // [step][B(64) | C(64)]

    const int tid  = threadIdx.x;
    const int lane = tid & 31;
    const int warp = tid >> 5;
    const int b    = blockIdx.x >> 6;           // 0..1
    const int d0   = (blockIdx.x & 63) * 32;    // channel base
    const int ch   = d0 + warp;                 // this warp's channel

    // A is diagonal per state; prefold log2(e): dA = exp2(dt * aL)
    constexpr float LOG2E = 1.4426950408889634f;
    const float a0L = -__expf(A_log[ch * D_STATE + 2 * lane])     * LOG2E;
    const float a1L = -__expf(A_log[ch * D_STATE + 2 * lane + 1]) * LOG2E;

    // store-phase constants (thread handles column sc = tid&31)
    const int   srow = tid >> 5;      // step within tile
    const int   scol = tid & 31;      // channel within block
    const float Dcol = Dvec[d0 + scol];

    const size_t rowL = (size_t)b * L_SEQ;
    const float* dtg = dt   + (rowL) * D_INNER + d0;
    const float* xg  = xact + (rowL) * D_INNER + d0;
    const float* zg  = xz   + (rowL) * (2 * D_INNER) + D_INNER + d0;
    const float* bcg = xdbl + (rowL) * XDBL_N + DT_RANK;
    float*       yg  = y    + (rowL) * D_INNER + d0;

    float h0 = 0.f, h1 = 0.f;

    for (int t0 = 0; t0 < L_SEQ; t0 += SC_TILE) {
        // ---- cooperative tile loads (all coalesced) ----
        {
            size_t g = (size_t)(t0 + srow) * D_INNER + scol;
            dt_s[srow][scol] = dtg[g];
            x_s [srow][scol] = xg[g];
            // B|C tile: 4096 floats, float4 per thread
            int r = tid >> 5, f = tid & 31;
            *(float4*)&bc_s[r][4 * f] =
                *(const float4*)(bcg + (size_t)(t0 + r) * XDBL_N + 4 * f);
        }
        __syncthreads();

        // ---- sequential recurrence for this warp's channel ----
#pragma unroll 4
        for (int j = 0; j < SC_TILE; j++) {
            float dtv = dt_s[j][warp];
            float xv  = x_s [j][warp];
            float2 bv = *(float2*)&bc_s[j][2 * lane];
            float2 cv = *(float2*)&bc_s[j][64 + 2 * lane];

            float du = dtv * xv;
            h0 = fmaf(h0, ex2(dtv * a0L), du * bv.x);
            h1 = fmaf(h1, ex2(dtv * a1L), du * bv.y);

            float ys = fmaf(h0, cv.x, h1 * cv.y);
#pragma unroll
            for (int o = 16; o; o >>= 1)
                ys += __shfl_xor_sync(0xffffffffu, ys, o);

            if (lane == 0) y_s[j][warp] = ys;
        }
        __syncthreads();

        // ---- gated, rounded, coalesced y-tile store ----
        {
            size_t g  = (size_t)(t0 + srow) * D_INNER + scol;
            float  zv = zg[(size_t)(t0 + srow) * (2 * D_INNER) + scol];
            float  sz = zv / (1.f + __expf(-zv));
            float  yv = (y_s[srow][scol] + Dcol * x_s[srow][scol]) * sz;
            yg[g] = to_tf32(yv);
        }
        __syncthreads();
    }
}

// ---------------- launch ----------------
extern "C" void kernel_launch(void* const* d_in, const int* in_sizes, int n_in,
                              void* d_out, int out_size)
{
    const float* hs        = (const float*)d_in[0];
    const float* in_proj_w = (const float*)d_in[1];
    const float* conv_w    = (const float*)d_in[2];
    const float* conv_b    = (const float*)d_in[3];
    const float* x_proj_w  = (const float*)d_in[4];
    const float* dt_proj_w = (const float*)d_in[5];
    const float* dt_proj_b = (const float*)d_in[6];
    const float* A_log     = (const float*)d_in[7];
    const float* Dv        = (const float*)d_in[8];
    const float* out_proj_w= (const float*)d_in[9];
    float* out = (float*)d_out;

    float *xz, *xact, *xact_r, *xdbl, *dtb, *yb, *hs_r, *wi_r, *wx_r, *wo_r;
    cudaGetSymbolAddress((void**)&xz,     g_xz);
    cudaGetSymbolAddress((void**)&xact,   g_xact);
    cudaGetSymbolAddress((void**)&xact_r, g_xact_r);
    cudaGetSymbolAddress((void**)&xdbl,   g_xdbl);
    cudaGetSymbolAddress((void**)&dtb,    g_dt);
    cudaGetSymbolAddress((void**)&yb,     g_y);
    cudaGetSymbolAddress((void**)&hs_r,   g_hs_r);
    cudaGetSymbolAddress((void**)&wi_r,   g_wi_r);
    cudaGetSymbolAddress((void**)&wx_r,   g_wx_r);
    cudaGetSymbolAddress((void**)&wo_r,   g_wo_r);

    cudaFuncSetAttribute(gemm_tc, cudaFuncAttributeMaxDynamicSharedMemorySize, GEMM_SMEM);

    // 0) round GEMM operands to tf32 (RNA)
    {
        int n4;
        n4 = ROWS * D_MODEL / 4;
        round_tf32_kernel<<<(n4 + 255) / 256, 256>>>(hs, hs_r, n4);
        n4 = 2 * D_INNER * D_MODEL / 4;
        round_tf32_kernel<<<(n4 + 255) / 256, 256>>>(in_proj_w, wi_r, n4);
        n4 = XDBL_N * D_INNER / 4;
        round_tf32_kernel<<<(n4 + 255) / 256, 256>>>(x_proj_w, wx_r, n4);
        n4 = D_MODEL * D_INNER / 4;
        round_tf32_kernel<<<(n4 + 255) / 256, 256>>>(out_proj_w, wo_r, n4);
    }

    // 1) xz = hs @ in_proj_w^T   [8192 x 4096]
    gemm_tc<<<dim3((2 * D_INNER) / 128, ROWS / 128), 256, GEMM_SMEM>>>(
        D_MODEL, hs_r, D_MODEL, wi_r, D_MODEL, xz, 2 * D_INNER);

    // 2) x = silu(causal_conv4(x) + b)
    {
        int total = B_SZ * L_SEQ * D_INNER;
        conv_silu_kernel<<<(total + 255) / 256, 256>>>(xz, conv_w, conv_b, xact, xact_r);
    }

    // 3) x_dbl = x @ x_proj_w^T   [8192 x 256]
    gemm_tc<<<dim3(XDBL_N / 128, ROWS / 128), 256, GEMM_SMEM>>>(
        D_INNER, xact_r, D_INNER, wx_r, D_INNER, xdbl, XDBL_N);

    // 4) dt = softplus(dt_low @ dt_proj_w^T + dt_proj_b)  (fp32 SIMT)
    sgemm_nt<1><<<dim3(D_INNER / 128, ROWS / 128), 256>>>(
        ROWS, D_INNER, DT_RANK, xdbl, XDBL_N, dt_proj_w, dt_proj_b, dtb, D_INNER);

    // 5) selective scan + gating epilogue -> yb
    scan_kernel<<<B_SZ * (D_INNER / 32), 1024>>>(dtb, xact, xdbl, xz, A_log, Dv, yb);

    // 6) out = y @ out_proj_w^T   [8192 x 1024]
    gemm_tc<<<dim3(D_MODEL / 128, ROWS / 128), 256, GEMM_SMEM>>>(
        D_INNER, yb, D_INNER, wo_r, D_INNER, out, D_MODEL);
}